// round 16
// baseline (speedup 1.0000x reference)
#include <cuda_runtime.h>
#include <cuda_bf16.h>
#include <stdint.h>

#define Bdim 256
#define Ddim 4096
#define MAXR 31

// ---------------- scratch ----------------
__device__ float    g_sc_x[Bdim * Ddim];
__device__ float    g_sc_y[Bdim * Ddim];
__device__ float    g_y[Bdim * Ddim];
__device__ int      g_idx[Bdim * MAXR];
__device__ int      g_radius[Bdim];
__device__ float    g_uacc[Bdim];
__device__ uint32_t g_stepkeys[2 * MAXR];
__device__ __nv_bfloat16 g_Whi[(size_t)Ddim * Ddim];
__device__ __nv_bfloat16 g_Wlo[(size_t)Ddim * Ddim];
__device__ __nv_bfloat16 g_xbf[Bdim * Ddim];

// ---------------- threefry2x32 (20 rounds) ----------------
__device__ __forceinline__ void tf2x32(uint32_t k0, uint32_t k1, uint32_t c0, uint32_t c1,
                                       uint32_t& o0, uint32_t& o1) {
    uint32_t ks2 = k0 ^ k1 ^ 0x1BD11BDAu;
    uint32_t x0 = c0 + k0, x1 = c1 + k1;
#define TFR(r) { x0 += x1; x1 = (x1 << (r)) | (x1 >> (32 - (r))); x1 ^= x0; }
    TFR(13) TFR(15) TFR(26) TFR(6)
    x0 += k1;  x1 += ks2 + 1u;
    TFR(17) TFR(29) TFR(16) TFR(24)
    x0 += ks2; x1 += k0 + 2u;
    TFR(13) TFR(15) TFR(26) TFR(6)
    x0 += k0;  x1 += k1 + 3u;
    TFR(17) TFR(29) TFR(16) TFR(24)
    x0 += k1;  x1 += ks2 + 4u;
    TFR(13) TFR(15) TFR(26) TFR(6)
    x0 += ks2; x1 += k0 + 5u;
#undef TFR
    o0 = x0; o1 = x1;
}

__device__ __forceinline__ uint32_t tf_bits32(uint32_t k0, uint32_t k1, uint32_t c1) {
    uint32_t a, b;
    tf2x32(k0, k1, 0u, c1, a, b);
    return a ^ b;
}
__device__ __forceinline__ float bits_to_u01f(uint32_t bits) {
    return __uint_as_float((bits >> 9) | 0x3f800000u) - 1.0f;
}

// ---------------- K1: prep — W split + x->bf16 + RNG setup ----------------
__global__ void __launch_bounds__(256) prep_kernel(const float* __restrict__ W,
                                                   const float* __restrict__ x) {
    int t = threadIdx.x;
    size_t i = ((size_t)blockIdx.x * 256 + t) * 4;
    float4 w = *(const float4*)(W + i);
    __nv_bfloat16 h[4], l[4];
    const float* wv = &w.x;
#pragma unroll
    for (int c = 0; c < 4; c++) {
        h[c] = __float2bfloat16_rn(wv[c]);
        l[c] = __float2bfloat16_rn(wv[c] - __bfloat162float(h[c]));
    }
    *(uint2*)(g_Whi + i) = *(uint2*)h;
    *(uint2*)(g_Wlo + i) = *(uint2*)l;

    if (blockIdx.x < (Bdim * Ddim) / (256 * 4)) {
        float4 v = *(const float4*)(x + i);
        __nv_bfloat16 o[4] = {__float2bfloat16_rn(v.x), __float2bfloat16_rn(v.y),
                              __float2bfloat16_rn(v.z), __float2bfloat16_rn(v.w)};
        *(uint2*)(g_xbf + i) = *(uint2*)o;
    }

    if (blockIdx.x == 0) {
        uint32_t kr0, kr1, ks0, ks1, ka0, ka1;
        tf2x32(0u, 42u, 0u, 0u, kr0, kr1);
        tf2x32(0u, 42u, 0u, 1u, ks0, ks1);
        tf2x32(0u, 42u, 0u, 2u, ka0, ka1);
        if (t < MAXR) {
            uint32_t a, b;
            tf2x32(ks0, ks1, 0u, (uint32_t)t, a, b);
            g_stepkeys[2 * t] = a;
            g_stepkeys[2 * t + 1] = b;
        }
        uint32_t ra0, ra1, rb0, rb1;
        tf2x32(kr0, kr1, 0u, 0u, ra0, ra1);
        tf2x32(kr0, kr1, 0u, 1u, rb0, rb1);
        uint32_t hi = tf_bits32(ra0, ra1, (uint32_t)t);
        uint32_t lo = tf_bits32(rb0, rb1, (uint32_t)t);
        uint32_t off = ((hi % 31u) * 4u + (lo % 31u)) % 31u;
        g_radius[t] = 1 + (int)off;
        uint32_t ub = tf_bits32(ka0, ka1, (uint32_t)t);
        g_uacc[t] = bits_to_u01f(ub);
    }
}

// ---------------- K2: tensor-core GEMM (R13 geometry: BM=64,BN=64,NSTG=3; race-safe commits) ----------------
#define BM 64
#define BN 64
#define BK 32
#define NSTG 3
#define ASTRIDE (BK + 8)
#define BSTRIDE (BN + 8)
#define KT (Ddim / BK)

__device__ __forceinline__ uint32_t smem_u32(const void* p) {
    return (uint32_t)__cvta_generic_to_shared(p);
}
#define CP_ASYNC16(dst, src) \
    asm volatile("cp.async.cg.shared.global [%0], [%1], 16;" :: "r"(dst), "l"(src))
#define CP_COMMIT() asm volatile("cp.async.commit_group;")
#define CP_WAIT1()  asm volatile("cp.async.wait_group 1;")
#define CP_WAITALL() asm volatile("cp.async.wait_group 0;")

#define LDSM_X4(r0, r1, r2, r3, addr) \
    asm volatile("ldmatrix.sync.aligned.m8n8.x4.shared.b16 {%0,%1,%2,%3}, [%4];" \
                 : "=r"(r0), "=r"(r1), "=r"(r2), "=r"(r3) : "r"(addr))
#define LDSM_X4_T(r0, r1, r2, r3, addr) \
    asm volatile("ldmatrix.sync.aligned.m8n8.x4.trans.shared.b16 {%0,%1,%2,%3}, [%4];" \
                 : "=r"(r0), "=r"(r1), "=r"(r2), "=r"(r3) : "r"(addr))
#define MMA_BF16(c0, c1, c2, c3, a0, a1, a2, a3, b0, b1) \
    asm volatile("mma.sync.aligned.m16n8k16.row.col.f32.bf16.bf16.f32 " \
                 "{%0,%1,%2,%3},{%4,%5,%6,%7},{%8,%9},{%0,%1,%2,%3};" \
                 : "+f"(c0), "+f"(c1), "+f"(c2), "+f"(c3) \
                 : "r"(a0), "r"(a1), "r"(a2), "r"(a3), "r"(b0), "r"(b1))

__global__ void __launch_bounds__(256) gemm_mma_kernel(const float* __restrict__ x,
                                                       const float* __restrict__ bias) {
    __shared__ __nv_bfloat16 As[NSTG][BM][ASTRIDE];
    __shared__ __nv_bfloat16 Bh[NSTG][BK][BSTRIDE];
    __shared__ __nv_bfloat16 Bl[NSTG][BK][BSTRIDE];

    int tid = threadIdx.x;
    int lane = tid & 31, wid = tid >> 5;
    int warp_m = wid >> 2;   // 0..1 : 32 rows
    int warp_n = wid & 3;    // 0..3 : 16 cols
    int m0 = blockIdx.y * BM;
    int n0 = blockIdx.x * BN;

    float acc[2][2][4];
#pragma unroll
    for (int i = 0; i < 2; i++)
#pragma unroll
        for (int j = 0; j < 2; j++)
#pragma unroll
            for (int c = 0; c < 4; c++) acc[i][j][c] = 0.0f;

    int ar = tid >> 2, ac = (tid & 3) * 8;   // A: 64 rows x 4 16B chunks
    int br = tid >> 3, bc = (tid & 7) * 8;   // B: 32 rows x 8 16B chunks

    const __nv_bfloat16* gA  = g_xbf + (size_t)(m0 + ar) * Ddim + ac;
    const __nv_bfloat16* gBh = g_Whi + (size_t)br * Ddim + n0 + bc;
    const __nv_bfloat16* gBl = g_Wlo + (size_t)br * Ddim + n0 + bc;

#define STAGE_LOAD_BODY(s, kt_) do { \
        size_t koff = (size_t)(kt_) * BK; \
        CP_ASYNC16(smem_u32(&As[s][ar][ac]), gA + koff); \
        CP_ASYNC16(smem_u32(&Bh[s][br][bc]), gBh + koff * Ddim); \
        CP_ASYNC16(smem_u32(&Bl[s][br][bc]), gBl + koff * Ddim); \
    } while (0)

    STAGE_LOAD_BODY(0, 0); CP_COMMIT();
    STAGE_LOAD_BODY(1, 1); CP_COMMIT();

    for (int kt = 0; kt < KT; kt++) {
        int buf = kt % NSTG;
        CP_WAIT1();
        __syncthreads();
        if (kt + 2 < KT) STAGE_LOAD_BODY((kt + 2) % NSTG, kt + 2);
        CP_COMMIT();   // ALWAYS commit (empty at tail): at iter kt, groups 0..kt+1
                       // committed -> wait_group 1 guarantees group kt done.

#pragma unroll
        for (int ks = 0; ks < 2; ks++) {
            uint32_t a[2][4];
#pragma unroll
            for (int mh = 0; mh < 2; mh++) {
                uint32_t addr = smem_u32(&As[buf][warp_m * 32 + mh * 16 + (lane & 15)][(lane >> 4) * 8 + ks * 16]);
                LDSM_X4(a[mh][0], a[mh][1], a[mh][2], a[mh][3], addr);
            }
            uint32_t bh[2][2], bl[2][2];
            {
                uint32_t r0, r1, r2, r3;
                uint32_t addrH = smem_u32(&Bh[buf][ks * 16 + (lane & 15)][warp_n * 16 + (lane >> 4) * 8]);
                LDSM_X4_T(r0, r1, r2, r3, addrH);
                bh[0][0] = r0; bh[0][1] = r1; bh[1][0] = r2; bh[1][1] = r3;
                uint32_t addrL = smem_u32(&Bl[buf][ks * 16 + (lane & 15)][warp_n * 16 + (lane >> 4) * 8]);
                LDSM_X4_T(r0, r1, r2, r3, addrL);
                bl[0][0] = r0; bl[0][1] = r1; bl[1][0] = r2; bl[1][1] = r3;
            }
#pragma unroll
            for (int mh = 0; mh < 2; mh++)
#pragma unroll
                for (int nq = 0; nq < 2; nq++) {
                    MMA_BF16(acc[mh][nq][0], acc[mh][nq][1], acc[mh][nq][2], acc[mh][nq][3],
                             a[mh][0], a[mh][1], a[mh][2], a[mh][3], bh[nq][0], bh[nq][1]);
                    MMA_BF16(acc[mh][nq][0], acc[mh][nq][1], acc[mh][nq][2], acc[mh][nq][3],
                             a[mh][0], a[mh][1], a[mh][2], a[mh][3], bl[nq][0], bl[nq][1]);
                }
        }
    }
    CP_WAITALL();

    // epilogue
#pragma unroll
    for (int mh = 0; mh < 2; mh++) {
#pragma unroll
        for (int nq = 0; nq < 2; nq++) {
            int rbase = m0 + warp_m * 32 + mh * 16 + (lane >> 2);
            int cbase = n0 + warp_n * 16 + nq * 8 + 2 * (lane & 3);
#pragma unroll
            for (int half = 0; half < 2; half++) {
                int r = rbase + half * 8;
                float v0 = acc[mh][nq][half * 2];
                float v1 = acc[mh][nq][half * 2 + 1];
                float b0 = bias[cbase], b1 = bias[cbase + 1];
                float x0 = x[(size_t)r * Ddim + cbase];
                float x1 = x[(size_t)r * Ddim + cbase + 1];
                float2 o;
                o.x = 0.5f * (1.0f - 2.0f * x0) * (v0 + b0);
                o.y = 0.5f * (1.0f - 2.0f * x1) * (v1 + b1);
                *(float2*)(g_sc_x + (size_t)r * Ddim + cbase) = o;
            }
        }
    }
}

// ---------------- K3: scan — surrogate argmin ----------------
__global__ void __launch_bounds__(512) scan_kernel(const float* __restrict__ x) {
    int b = blockIdx.x, t = threadIdx.x;
    __shared__ float2 sVI[2][16];
    __shared__ uint32_t skey[2 * MAXR];

    if (t < 2 * MAXR) skey[t] = g_stepkeys[t];

    float negE[8];
#pragma unroll
    for (int i = 0; i < 8; i++) {
        float sc = g_sc_x[(size_t)b * Ddim + t + 512 * i];
        negE[i] = -expf(-sc);
    }
    int rad = g_radius[b];
    uint32_t myflip = 0;
    __syncthreads();

    int lane = t & 31, w = t >> 5;
    uint32_t cbase = (uint32_t)(b * Ddim + t);
    for (int j = 0; j < MAXR; j++) {
        uint32_t kx = skey[2 * j], ky = skey[2 * j + 1];
        int p = j & 1;
        float bv = INFINITY;
        int bi = Ddim;
#pragma unroll
        for (int i = 0; i < 8; i++) {
            uint32_t bits = tf_bits32(kx, ky, cbase + 512u * i);
            float u = fmaxf(bits_to_u01f(bits), 1.17549435e-38f);
            float v = logf(u) * negE[i];
            if (v < bv) { bv = v; bi = t + 512 * i; }
        }
#pragma unroll
        for (int off = 16; off > 0; off >>= 1) {
            float ov = __shfl_down_sync(0xffffffffu, bv, off);
            int oi = __shfl_down_sync(0xffffffffu, bi, off);
            if (ov < bv || (ov == bv && oi < bi)) { bv = ov; bi = oi; }
        }
        if (lane == 0) sVI[p][w] = make_float2(bv, __int_as_float(bi));
        __syncthreads();
        bv = INFINITY; bi = Ddim;
#pragma unroll
        for (int q = 0; q < 16; q++) {
            float2 c = sVI[p][q];
            int ci = __float_as_int(c.y);
            if (c.x < bv || (c.x == bv && ci < bi)) { bv = c.x; bi = ci; }
        }
        if ((bi & 511) == t) {
            int ii = bi >> 9;
#pragma unroll
            for (int i = 0; i < 8; i++)
                if (i == ii) {
                    negE[i] = -INFINITY;
                    if (j < rad) myflip |= (1u << i);
                }
        }
        if (t == 0) g_idx[b * MAXR + j] = bi;
    }
#pragma unroll
    for (int i = 0; i < 8; i++) {
        int d = t + 512 * i;
        float xv = x[(size_t)b * Ddim + d];
        g_y[(size_t)b * Ddim + d] = ((myflip >> i) & 1u) ? (1.0f - xv) : xv;
    }
}

// ---------------- K4: rank-<=31 update (frozen) ----------------
__global__ void __launch_bounds__(256) grady_kernel(const float* __restrict__ x,
                                                    const float* __restrict__ W) {
    int b = blockIdx.y;
    int d = blockIdx.x * 256 + threadIdx.x;
    const float* xr = x + (size_t)b * Ddim;
    float scx = g_sc_x[(size_t)b * Ddim + d];
    float xv = xr[d];
    float g = 2.0f * (1.0f - 2.0f * xv) * scx;
    int rad = g_radius[b];
    for (int j = 0; j < rad; j++) {
        int i = g_idx[b * MAXR + j];
        float delta = 1.0f - 2.0f * xr[i];
        g += delta * W[(size_t)i * Ddim + d];
    }
    float yv = g_y[(size_t)b * Ddim + d];
    g_sc_y[(size_t)b * Ddim + d] = 0.5f * (1.0f - 2.0f * yv) * g;
}

// ---------------- K5: scores + acceptance + output write (frozen) ----------------
__global__ void __launch_bounds__(256) finalize_kernel(const float* __restrict__ x,
                                                       const float* __restrict__ bias,
                                                       float* __restrict__ out) {
    int b = blockIdx.x, t = threadIdx.x;
    __shared__ float sf[256];
    __shared__ double sd[256];
    __shared__ int sAcc;

    float mx = -INFINITY, my = -INFINITY;
    for (int i = 0; i < 16; i++) {
        int d = t + 256 * i;
        mx = fmaxf(mx, g_sc_x[(size_t)b * Ddim + d]);
        my = fmaxf(my, g_sc_y[(size_t)b * Ddim + d]);
    }
    sf[t] = mx; __syncthreads();
    for (int s = 128; s > 0; s >>= 1) { if (t < s) sf[t] = fmaxf(sf[t], sf[t + s]); __syncthreads(); }
    float Mx = sf[0]; __syncthreads();
    sf[t] = my; __syncthreads();
    for (int s = 128; s > 0; s >>= 1) { if (t < s) sf[t] = fmaxf(sf[t], sf[t + s]); __syncthreads(); }
    float My = sf[0]; __syncthreads();

    double sfx = 0, sfy = 0, sx1 = 0, sbx = 0, sy1 = 0, sby = 0;
    for (int i = 0; i < 16; i++) {
        int d = t + 256 * i;
        float scx = g_sc_x[(size_t)b * Ddim + d];
        float scy = g_sc_y[(size_t)b * Ddim + d];
        float xv = x[(size_t)b * Ddim + d];
        float yv = g_y[(size_t)b * Ddim + d];
        float bb = bias[d];
        sfx += (double)expf(scx - Mx);
        sfy += (double)expf(scy - My);
        if (xv > 0.5f) { sx1 += (double)scx; sbx += (double)bb; }
        if (yv > 0.5f) { sy1 += (double)scy; sby += (double)bb; }
    }
    auto red = [&](double v) -> double {
        sd[t] = v; __syncthreads();
        for (int s = 128; s > 0; s >>= 1) { if (t < s) sd[t] += sd[t + s]; __syncthreads(); }
        double r = sd[0]; __syncthreads();
        return r;
    };
    double Sfx = red(sfx), Sfy = red(sfy);
    double Sx1 = red(sx1), Sbx = red(sbx), Sy1 = red(sy1), Sby = red(sby);

    if (t == 0) {
        double score_x = -Sx1 + 0.5 * Sbx;
        double score_y = -Sy1 + 0.5 * Sby;
        int rad = g_radius[b];
        double scxi[MAXR], scyi[MAXR], efx[MAXR], efy[MAXR];
        for (int j = 0; j < MAXR; j++) {
            int i = g_idx[b * MAXR + j];
            scxi[j] = (double)g_sc_x[(size_t)b * Ddim + i];
            scyi[j] = (double)g_sc_y[(size_t)b * Ddim + i];
            efx[j] = exp(scxi[j] - (double)Mx);
            efy[j] = exp(scyi[j] - (double)My);
        }
        double pre = 0.0, sumf = 0.0;
        for (int j = 0; j < MAXR; j++) {
            double lse = (double)Mx + log(Sfx - pre);
            if (j < rad) sumf += scxi[j] - lse;
            pre += efx[j];
        }
        double suf = 0.0, sumb = 0.0;
        for (int j = MAXR - 1; j >= 0; j--) {
            double lse = (double)My + log(Sfy - suf);
            if (j < rad) sumb += scyi[j] - lse;
            suf += efy[j];
        }
        double la = (sumb + score_y) - (sumf + score_x);
        float ratio = expf((float)la);
        sAcc = (ratio >= g_uacc[b]) ? 1 : 0;
    }
    __syncthreads();
    int acc = sAcc;
    for (int i = 0; i < 16; i++) {
        int d = t + 256 * i;
        size_t idx = (size_t)b * Ddim + d;
        out[idx] = acc ? g_y[idx] : x[idx];
    }
}

// ---------------- launch ----------------
extern "C" void kernel_launch(void* const* d_in, const int* in_sizes, int n_in,
                              void* d_out, int out_size) {
    const float* x = (const float*)d_in[0];
    const float* W = (const float*)d_in[1];
    const float* bias = (const float*)d_in[2];
    float* out = (float*)d_out;

    prep_kernel<<<(Ddim * Ddim) / (256 * 4), 256>>>(W, x);           // 1
    gemm_mma_kernel<<<dim3(Ddim / BN, Bdim / BM), 256>>>(x, bias);   // 2
    scan_kernel<<<Bdim, 512>>>(x);                                   // 3
    grady_kernel<<<dim3(Ddim / 256, Bdim), 256>>>(x, W);             // 4
    finalize_kernel<<<Bdim, 256>>>(x, bias, out);                    // 5
}

// round 17
// speedup vs baseline: 1.5679x; 1.5679x over previous
#include <cuda_runtime.h>
#include <cuda_bf16.h>
#include <stdint.h>

#define Bdim 256
#define Ddim 4096
#define MAXR 31

// ---------------- scratch ----------------
__device__ float    g_sc_x[Bdim * Ddim];
__device__ float    g_sc_y[Bdim * Ddim];
__device__ float    g_y[Bdim * Ddim];
__device__ int      g_idx[Bdim * MAXR];
__device__ int      g_radius[Bdim];
__device__ float    g_uacc[Bdim];
__device__ uint32_t g_stepkeys[2 * MAXR];
__device__ __nv_bfloat16 g_Whi[(size_t)Ddim * Ddim];
__device__ __nv_bfloat16 g_Wlo[(size_t)Ddim * Ddim];
__device__ __nv_bfloat16 g_xbf[Bdim * Ddim];

// ---------------- threefry2x32 (20 rounds) ----------------
__device__ __forceinline__ void tf2x32(uint32_t k0, uint32_t k1, uint32_t c0, uint32_t c1,
                                       uint32_t& o0, uint32_t& o1) {
    uint32_t ks2 = k0 ^ k1 ^ 0x1BD11BDAu;
    uint32_t x0 = c0 + k0, x1 = c1 + k1;
#define TFR(r) { x0 += x1; x1 = (x1 << (r)) | (x1 >> (32 - (r))); x1 ^= x0; }
    TFR(13) TFR(15) TFR(26) TFR(6)
    x0 += k1;  x1 += ks2 + 1u;
    TFR(17) TFR(29) TFR(16) TFR(24)
    x0 += ks2; x1 += k0 + 2u;
    TFR(13) TFR(15) TFR(26) TFR(6)
    x0 += k0;  x1 += k1 + 3u;
    TFR(17) TFR(29) TFR(16) TFR(24)
    x0 += k1;  x1 += ks2 + 4u;
    TFR(13) TFR(15) TFR(26) TFR(6)
    x0 += ks2; x1 += k0 + 5u;
#undef TFR
    o0 = x0; o1 = x1;
}

__device__ __forceinline__ uint32_t tf_bits32(uint32_t k0, uint32_t k1, uint32_t c1) {
    uint32_t a, b;
    tf2x32(k0, k1, 0u, c1, a, b);
    return a ^ b;
}
__device__ __forceinline__ float bits_to_u01f(uint32_t bits) {
    return __uint_as_float((bits >> 9) | 0x3f800000u) - 1.0f;
}

// ---------------- K1: prep — W split + x->bf16 + RNG setup ----------------
__global__ void __launch_bounds__(256) prep_kernel(const float* __restrict__ W,
                                                   const float* __restrict__ x) {
    int t = threadIdx.x;
    size_t i = ((size_t)blockIdx.x * 256 + t) * 4;
    float4 w = *(const float4*)(W + i);
    __nv_bfloat16 h[4], l[4];
    const float* wv = &w.x;
#pragma unroll
    for (int c = 0; c < 4; c++) {
        h[c] = __float2bfloat16_rn(wv[c]);
        l[c] = __float2bfloat16_rn(wv[c] - __bfloat162float(h[c]));
    }
    *(uint2*)(g_Whi + i) = *(uint2*)h;
    *(uint2*)(g_Wlo + i) = *(uint2*)l;

    if (blockIdx.x < (Bdim * Ddim) / (256 * 4)) {
        float4 v = *(const float4*)(x + i);
        __nv_bfloat16 o[4] = {__float2bfloat16_rn(v.x), __float2bfloat16_rn(v.y),
                              __float2bfloat16_rn(v.z), __float2bfloat16_rn(v.w)};
        *(uint2*)(g_xbf + i) = *(uint2*)o;
    }

    if (blockIdx.x == 0) {
        uint32_t kr0, kr1, ks0, ks1, ka0, ka1;
        tf2x32(0u, 42u, 0u, 0u, kr0, kr1);
        tf2x32(0u, 42u, 0u, 1u, ks0, ks1);
        tf2x32(0u, 42u, 0u, 2u, ka0, ka1);
        if (t < MAXR) {
            uint32_t a, b;
            tf2x32(ks0, ks1, 0u, (uint32_t)t, a, b);
            g_stepkeys[2 * t] = a;
            g_stepkeys[2 * t + 1] = b;
        }
        uint32_t ra0, ra1, rb0, rb1;
        tf2x32(kr0, kr1, 0u, 0u, ra0, ra1);
        tf2x32(kr0, kr1, 0u, 1u, rb0, rb1);
        uint32_t hi = tf_bits32(ra0, ra1, (uint32_t)t);
        uint32_t lo = tf_bits32(rb0, rb1, (uint32_t)t);
        uint32_t off = ((hi % 31u) * 4u + (lo % 31u)) % 31u;
        g_radius[t] = 1 + (int)off;
        uint32_t ub = tf_bits32(ka0, ka1, (uint32_t)t);
        g_uacc[t] = bits_to_u01f(ub);
    }
}

// ---------------- K2: tensor-core GEMM (BM=64,BN=64,NSTG=3; race-safe commits) ----------------
#define BM 64
#define BN 64
#define BK 32
#define NSTG 3
#define ASTRIDE (BK + 8)
#define BSTRIDE (BN + 8)
#define KT (Ddim / BK)

__device__ __forceinline__ uint32_t smem_u32(const void* p) {
    return (uint32_t)__cvta_generic_to_shared(p);
}
#define CP_ASYNC16(dst, src) \
    asm volatile("cp.async.cg.shared.global [%0], [%1], 16;" :: "r"(dst), "l"(src))
#define CP_COMMIT() asm volatile("cp.async.commit_group;")
#define CP_WAIT1()  asm volatile("cp.async.wait_group 1;")
#define CP_WAITALL() asm volatile("cp.async.wait_group 0;")

#define LDSM_X4(r0, r1, r2, r3, addr) \
    asm volatile("ldmatrix.sync.aligned.m8n8.x4.shared.b16 {%0,%1,%2,%3}, [%4];" \
                 : "=r"(r0), "=r"(r1), "=r"(r2), "=r"(r3) : "r"(addr))
#define LDSM_X4_T(r0, r1, r2, r3, addr) \
    asm volatile("ldmatrix.sync.aligned.m8n8.x4.trans.shared.b16 {%0,%1,%2,%3}, [%4];" \
                 : "=r"(r0), "=r"(r1), "=r"(r2), "=r"(r3) : "r"(addr))
#define MMA_BF16(c0, c1, c2, c3, a0, a1, a2, a3, b0, b1) \
    asm volatile("mma.sync.aligned.m16n8k16.row.col.f32.bf16.bf16.f32 " \
                 "{%0,%1,%2,%3},{%4,%5,%6,%7},{%8,%9},{%0,%1,%2,%3};" \
                 : "+f"(c0), "+f"(c1), "+f"(c2), "+f"(c3) \
                 : "r"(a0), "r"(a1), "r"(a2), "r"(a3), "r"(b0), "r"(b1))

__global__ void __launch_bounds__(256) gemm_mma_kernel(const float* __restrict__ x,
                                                       const float* __restrict__ bias) {
    __shared__ __nv_bfloat16 As[NSTG][BM][ASTRIDE];
    __shared__ __nv_bfloat16 Bh[NSTG][BK][BSTRIDE];
    __shared__ __nv_bfloat16 Bl[NSTG][BK][BSTRIDE];

    int tid = threadIdx.x;
    int lane = tid & 31, wid = tid >> 5;
    int warp_m = wid >> 2;   // 0..1 : 32 rows
    int warp_n = wid & 3;    // 0..3 : 16 cols
    int m0 = blockIdx.y * BM;
    int n0 = blockIdx.x * BN;

    float acc[2][2][4];
#pragma unroll
    for (int i = 0; i < 2; i++)
#pragma unroll
        for (int j = 0; j < 2; j++)
#pragma unroll
            for (int c = 0; c < 4; c++) acc[i][j][c] = 0.0f;

    int ar = tid >> 2, ac = (tid & 3) * 8;   // A: 64 rows x 4 16B chunks
    int br = tid >> 3, bc = (tid & 7) * 8;   // B: 32 rows x 8 16B chunks

    const __nv_bfloat16* gA  = g_xbf + (size_t)(m0 + ar) * Ddim + ac;
    const __nv_bfloat16* gBh = g_Whi + (size_t)br * Ddim + n0 + bc;
    const __nv_bfloat16* gBl = g_Wlo + (size_t)br * Ddim + n0 + bc;

#define STAGE_LOAD_BODY(s, kt_) do { \
        size_t koff = (size_t)(kt_) * BK; \
        CP_ASYNC16(smem_u32(&As[s][ar][ac]), gA + koff); \
        CP_ASYNC16(smem_u32(&Bh[s][br][bc]), gBh + koff * Ddim); \
        CP_ASYNC16(smem_u32(&Bl[s][br][bc]), gBl + koff * Ddim); \
    } while (0)

    STAGE_LOAD_BODY(0, 0); CP_COMMIT();
    STAGE_LOAD_BODY(1, 1); CP_COMMIT();

    for (int kt = 0; kt < KT; kt++) {
        int buf = kt % NSTG;
        CP_WAIT1();
        __syncthreads();
        if (kt + 2 < KT) STAGE_LOAD_BODY((kt + 2) % NSTG, kt + 2);
        CP_COMMIT();   // ALWAYS commit (empty at tail): groups 0..kt+1 committed
                       // at iter kt -> wait_group 1 guarantees group kt done.

#pragma unroll
        for (int ks = 0; ks < 2; ks++) {
            uint32_t a[2][4];
#pragma unroll
            for (int mh = 0; mh < 2; mh++) {
                uint32_t addr = smem_u32(&As[buf][warp_m * 32 + mh * 16 + (lane & 15)][(lane >> 4) * 8 + ks * 16]);
                LDSM_X4(a[mh][0], a[mh][1], a[mh][2], a[mh][3], addr);
            }
            uint32_t bh[2][2], bl[2][2];
            {
                uint32_t r0, r1, r2, r3;
                uint32_t addrH = smem_u32(&Bh[buf][ks * 16 + (lane & 15)][warp_n * 16 + (lane >> 4) * 8]);
                LDSM_X4_T(r0, r1, r2, r3, addrH);
                bh[0][0] = r0; bh[0][1] = r1; bh[1][0] = r2; bh[1][1] = r3;
                uint32_t addrL = smem_u32(&Bl[buf][ks * 16 + (lane & 15)][warp_n * 16 + (lane >> 4) * 8]);
                LDSM_X4_T(r0, r1, r2, r3, addrL);
                bl[0][0] = r0; bl[0][1] = r1; bl[1][0] = r2; bl[1][1] = r3;
            }
#pragma unroll
            for (int mh = 0; mh < 2; mh++)
#pragma unroll
                for (int nq = 0; nq < 2; nq++) {
                    MMA_BF16(acc[mh][nq][0], acc[mh][nq][1], acc[mh][nq][2], acc[mh][nq][3],
                             a[mh][0], a[mh][1], a[mh][2], a[mh][3], bh[nq][0], bh[nq][1]);
                    MMA_BF16(acc[mh][nq][0], acc[mh][nq][1], acc[mh][nq][2], acc[mh][nq][3],
                             a[mh][0], a[mh][1], a[mh][2], a[mh][3], bl[nq][0], bl[nq][1]);
                }
        }
    }
    CP_WAITALL();

    // epilogue
#pragma unroll
    for (int mh = 0; mh < 2; mh++) {
#pragma unroll
        for (int nq = 0; nq < 2; nq++) {
            int rbase = m0 + warp_m * 32 + mh * 16 + (lane >> 2);
            int cbase = n0 + warp_n * 16 + nq * 8 + 2 * (lane & 3);
#pragma unroll
            for (int half = 0; half < 2; half++) {
                int r = rbase + half * 8;
                float v0 = acc[mh][nq][half * 2];
                float v1 = acc[mh][nq][half * 2 + 1];
                float b0 = bias[cbase], b1 = bias[cbase + 1];
                float x0 = x[(size_t)r * Ddim + cbase];
                float x1 = x[(size_t)r * Ddim + cbase + 1];
                float2 o;
                o.x = 0.5f * (1.0f - 2.0f * x0) * (v0 + b0);
                o.y = 0.5f * (1.0f - 2.0f * x1) * (v1 + b1);
                *(float2*)(g_sc_x + (size_t)r * Ddim + cbase) = o;
            }
        }
    }
}

// ---------------- K3: scan — surrogate argmin ----------------
__global__ void __launch_bounds__(512) scan_kernel(const float* __restrict__ x) {
    int b = blockIdx.x, t = threadIdx.x;
    __shared__ float2 sVI[2][16];
    __shared__ uint32_t skey[2 * MAXR];

    if (t < 2 * MAXR) skey[t] = g_stepkeys[t];

    float negE[8];
#pragma unroll
    for (int i = 0; i < 8; i++) {
        float sc = g_sc_x[(size_t)b * Ddim + t + 512 * i];
        negE[i] = -expf(-sc);
    }
    int rad = g_radius[b];
    uint32_t myflip = 0;
    __syncthreads();

    int lane = t & 31, w = t >> 5;
    uint32_t cbase = (uint32_t)(b * Ddim + t);
    for (int j = 0; j < MAXR; j++) {
        uint32_t kx = skey[2 * j], ky = skey[2 * j + 1];
        int p = j & 1;
        float bv = INFINITY;
        int bi = Ddim;
#pragma unroll
        for (int i = 0; i < 8; i++) {
            uint32_t bits = tf_bits32(kx, ky, cbase + 512u * i);
            float u = fmaxf(bits_to_u01f(bits), 1.17549435e-38f);
            float v = logf(u) * negE[i];
            if (v < bv) { bv = v; bi = t + 512 * i; }
        }
#pragma unroll
        for (int off = 16; off > 0; off >>= 1) {
            float ov = __shfl_down_sync(0xffffffffu, bv, off);
            int oi = __shfl_down_sync(0xffffffffu, bi, off);
            if (ov < bv || (ov == bv && oi < bi)) { bv = ov; bi = oi; }
        }
        if (lane == 0) sVI[p][w] = make_float2(bv, __int_as_float(bi));
        __syncthreads();
        bv = INFINITY; bi = Ddim;
#pragma unroll
        for (int q = 0; q < 16; q++) {
            float2 c = sVI[p][q];
            int ci = __float_as_int(c.y);
            if (c.x < bv || (c.x == bv && ci < bi)) { bv = c.x; bi = ci; }
        }
        if ((bi & 511) == t) {
            int ii = bi >> 9;
#pragma unroll
            for (int i = 0; i < 8; i++)
                if (i == ii) {
                    negE[i] = -INFINITY;
                    if (j < rad) myflip |= (1u << i);
                }
        }
        if (t == 0) g_idx[b * MAXR + j] = bi;
    }
#pragma unroll
    for (int i = 0; i < 8; i++) {
        int d = t + 512 * i;
        float xv = x[(size_t)b * Ddim + d];
        g_y[(size_t)b * Ddim + d] = ((myflip >> i) & 1u) ? (1.0f - xv) : xv;
    }
}

// ---------------- K4: rank-<=31 update (frozen) ----------------
__global__ void __launch_bounds__(256) grady_kernel(const float* __restrict__ x,
                                                    const float* __restrict__ W) {
    int b = blockIdx.y;
    int d = blockIdx.x * 256 + threadIdx.x;
    const float* xr = x + (size_t)b * Ddim;
    float scx = g_sc_x[(size_t)b * Ddim + d];
    float xv = xr[d];
    float g = 2.0f * (1.0f - 2.0f * xv) * scx;
    int rad = g_radius[b];
    for (int j = 0; j < rad; j++) {
        int i = g_idx[b * MAXR + j];
        float delta = 1.0f - 2.0f * xr[i];
        g += delta * W[(size_t)i * Ddim + d];
    }
    float yv = g_y[(size_t)b * Ddim + d];
    g_sc_y[(size_t)b * Ddim + d] = 0.5f * (1.0f - 2.0f * yv) * g;
}

// ---------------- K5: scores + acceptance + output write (frozen) ----------------
__global__ void __launch_bounds__(256) finalize_kernel(const float* __restrict__ x,
                                                       const float* __restrict__ bias,
                                                       float* __restrict__ out) {
    int b = blockIdx.x, t = threadIdx.x;
    __shared__ float sf[256];
    __shared__ double sd[256];
    __shared__ int sAcc;

    float mx = -INFINITY, my = -INFINITY;
    for (int i = 0; i < 16; i++) {
        int d = t + 256 * i;
        mx = fmaxf(mx, g_sc_x[(size_t)b * Ddim + d]);
        my = fmaxf(my, g_sc_y[(size_t)b * Ddim + d]);
    }
    sf[t] = mx; __syncthreads();
    for (int s = 128; s > 0; s >>= 1) { if (t < s) sf[t] = fmaxf(sf[t], sf[t + s]); __syncthreads(); }
    float Mx = sf[0]; __syncthreads();
    sf[t] = my; __syncthreads();
    for (int s = 128; s > 0; s >>= 1) { if (t < s) sf[t] = fmaxf(sf[t], sf[t + s]); __syncthreads(); }
    float My = sf[0]; __syncthreads();

    double sfx = 0, sfy = 0, sx1 = 0, sbx = 0, sy1 = 0, sby = 0;
    for (int i = 0; i < 16; i++) {
        int d = t + 256 * i;
        float scx = g_sc_x[(size_t)b * Ddim + d];
        float scy = g_sc_y[(size_t)b * Ddim + d];
        float xv = x[(size_t)b * Ddim + d];
        float yv = g_y[(size_t)b * Ddim + d];
        float bb = bias[d];
        sfx += (double)expf(scx - Mx);
        sfy += (double)expf(scy - My);
        if (xv > 0.5f) { sx1 += (double)scx; sbx += (double)bb; }
        if (yv > 0.5f) { sy1 += (double)scy; sby += (double)bb; }
    }
    auto red = [&](double v) -> double {
        sd[t] = v; __syncthreads();
        for (int s = 128; s > 0; s >>= 1) { if (t < s) sd[t] += sd[t + s]; __syncthreads(); }
        double r = sd[0]; __syncthreads();
        return r;
    };
    double Sfx = red(sfx), Sfy = red(sfy);
    double Sx1 = red(sx1), Sbx = red(sbx), Sy1 = red(sy1), Sby = red(sby);

    if (t == 0) {
        double score_x = -Sx1 + 0.5 * Sbx;
        double score_y = -Sy1 + 0.5 * Sby;
        int rad = g_radius[b];
        double scxi[MAXR], scyi[MAXR], efx[MAXR], efy[MAXR];
        for (int j = 0; j < MAXR; j++) {
            int i = g_idx[b * MAXR + j];
            scxi[j] = (double)g_sc_x[(size_t)b * Ddim + i];
            scyi[j] = (double)g_sc_y[(size_t)b * Ddim + i];
            efx[j] = exp(scxi[j] - (double)Mx);
            efy[j] = exp(scyi[j] - (double)My);
        }
        double pre = 0.0, sumf = 0.0;
        for (int j = 0; j < MAXR; j++) {
            double lse = (double)Mx + log(Sfx - pre);
            if (j < rad) sumf += scxi[j] - lse;
            pre += efx[j];
        }
        double suf = 0.0, sumb = 0.0;
        for (int j = MAXR - 1; j >= 0; j--) {
            double lse = (double)My + log(Sfy - suf);
            if (j < rad) sumb += scyi[j] - lse;
            suf += efy[j];
        }
        double la = (sumb + score_y) - (sumf + score_x);
        float ratio = expf((float)la);
        sAcc = (ratio >= g_uacc[b]) ? 1 : 0;
    }
    __syncthreads();
    int acc = sAcc;
    for (int i = 0; i < 16; i++) {
        int d = t + 256 * i;
        size_t idx = (size_t)b * Ddim + d;
        out[idx] = acc ? g_y[idx] : x[idx];
    }
}

// ---------------- launch ----------------
extern "C" void kernel_launch(void* const* d_in, const int* in_sizes, int n_in,
                              void* d_out, int out_size) {
    const float* x = (const float*)d_in[0];
    const float* W = (const float*)d_in[1];
    const float* bias = (const float*)d_in[2];
    float* out = (float*)d_out;

    prep_kernel<<<(Ddim * Ddim) / (256 * 4), 256>>>(W, x);           // 1
    gemm_mma_kernel<<<dim3(Ddim / BN, Bdim / BM), 256>>>(x, bias);   // 2
    scan_kernel<<<Bdim, 512>>>(x);                                   // 3
    grady_kernel<<<dim3(Ddim / 256, Bdim), 256>>>(x, W);             // 4
    finalize_kernel<<<Bdim, 256>>>(x, bias, out);                    // 5
}